// round 8
// baseline (speedup 1.0000x reference)
#include <cuda_runtime.h>
#include <math.h>

// out[n,j] = (x[n]==0 ? 0 : W[x[n],j]) + pe(n+1, j)
// pe(pos,j): even j -> cos(pos*w_{j/2}); odd j -> sin(pos*w_{(j+1)/2}); w_m = 1e-4^(m/512)
// Thread t owns cols 4t..4t+3. Warp-uniform EXACT (sincosf) / ROTATE (12 FMA) pe paths.
//
// R7: same double-buffered cp.async gather as R5/R6 (register-free MLP, no
// __syncthreads needed since each thread consumes only its own copies), but with
// plain cp.async.cg — createpolicy/L2::cache_hint removed after two container-level
// bench failures (de-risking the only exotic instruction vs the known-good R4 run).
// Drain rule: final iteration waits group 0.

#define DHID 1024
#define TPB 256
#define ROWS_PER_CTA 32
#define CHUNK 4
#define STAGES 2
#define NCHUNK (ROWS_PER_CTA / CHUNK)
#define ANGLE_T 3000.0f

__global__ __launch_bounds__(TPB)
void pe_embed_kernel(const int* __restrict__ x,
                     const float4* __restrict__ W4,
                     float4* __restrict__ out4,
                     int N)
{
    __shared__ float4 buf[STAGES][CHUNK * TPB];   // 32 KB

    const int t    = threadIdx.x;
    const int lane = t & 31;
    const long long row0 = (long long)blockIdx.x * (long long)ROWS_PER_CTA;
    if (row0 >= N) return;
    const long long rend = (row0 + ROWS_PER_CTA < (long long)N) ? row0 + ROWS_PER_CTA
                                                                : (long long)N;

    const float base   = 1.0f / 10000.0f;
    const float inv512 = 1.0f / 512.0f;
    const float w0 = powf(base, (float)(2 * t    ) * inv512);
    const float w1 = powf(base, (float)(2 * t + 1) * inv512);
    const float w2 = powf(base, (float)(2 * t + 2) * inv512);

    const float wmax  = __shfl_sync(0xFFFFFFFFu, w0, 0);
    const bool  exact = ((float)rend * wmax) > ANGLE_T;

    if ((rend - row0) == ROWS_PER_CTA) {
        int idxs[STAGES][CHUNK];

        #define ISSUE(c, s)                                                          \
            {                                                                        \
                _Pragma("unroll")                                                    \
                for (int k = 0; k < CHUNK; ++k) {                                    \
                    int id = __ldg(&x[row0 + (long long)(c) * CHUNK + k]);           \
                    idxs[(s)][k] = id;                                               \
                    const float4* srcp = &W4[(long long)id * (DHID / 4) + t];        \
                    unsigned dst = (unsigned)__cvta_generic_to_shared(               \
                        &buf[(s)][k * TPB + t]);                                     \
                    asm volatile(                                                    \
                        "cp.async.cg.shared.global [%0], [%1], 16;"                  \
                        :: "r"(dst), "l"(srcp) : "memory");                          \
                }                                                                    \
                asm volatile("cp.async.commit_group;" ::: "memory");                 \
            }

        // Drain rule: at iter c, committed = min(c+2, NCHUNK); group c must be done
        // => allowed pending = 1 for c < NCHUNK-1, 0 for the last iteration.
        #define WAITC(c)                                                             \
            {                                                                        \
                if ((c) == NCHUNK - 1)                                               \
                    asm volatile("cp.async.wait_group 0;" ::: "memory");             \
                else                                                                 \
                    asm volatile("cp.async.wait_group 1;" ::: "memory");             \
            }

        ISSUE(0, 0);
        ISSUE(1, 1);

        if (exact) {
            #pragma unroll
            for (int c = 0; c < NCHUNK; ++c) {
                const int s = c & 1;
                WAITC(c);
                float4 o[CHUNK];
                #pragma unroll
                for (int k = 0; k < CHUNK; ++k) {
                    float4 e = make_float4(0.f, 0.f, 0.f, 0.f);
                    if (idxs[s][k] != 0) e = buf[s][k * TPB + t];
                    const float pos = (float)(row0 + c * CHUNK + k + 1);
                    float sA, cA, sB, cB;
                    sincosf(pos * w1, &sA, &cA);
                    sincosf(pos * w2, &sB, &cB);
                    float c0v = __shfl_up_sync(0xFFFFFFFFu, cB, 1);
                    if (lane == 0) c0v = cosf(pos * w0);
                    o[k].x = e.x + c0v;
                    o[k].y = e.y + sA;
                    o[k].z = e.z + cA;
                    o[k].w = e.w + sB;
                }
                if (c + STAGES < NCHUNK) ISSUE(c + STAGES, s);
                #pragma unroll
                for (int k = 0; k < CHUNK; ++k)
                    __stcs(&out4[(row0 + c * CHUNK + k) * (DHID / 4) + t], o[k]);
            }
        } else {
            const float pos0 = (float)(row0 + 1);
            float s0, c0, s1, c1, s2, c2;
            sincosf(pos0 * w0, &s0, &c0);
            sincosf(pos0 * w1, &s1, &c1);
            sincosf(pos0 * w2, &s2, &c2);
            float sw0, cw0, sw1, cw1, sw2, cw2;
            sincosf(w0, &sw0, &cw0);
            sincosf(w1, &sw1, &cw1);
            sincosf(w2, &sw2, &cw2);

            #pragma unroll
            for (int c = 0; c < NCHUNK; ++c) {
                const int s = c & 1;
                WAITC(c);
                float4 o[CHUNK];
                #pragma unroll
                for (int k = 0; k < CHUNK; ++k) {
                    float4 e = make_float4(0.f, 0.f, 0.f, 0.f);
                    if (idxs[s][k] != 0) e = buf[s][k * TPB + t];
                    o[k].x = e.x + c0;
                    o[k].y = e.y + s1;
                    o[k].z = e.z + c1;
                    o[k].w = e.w + s2;

                    float ns0 = fmaf(s0, cw0,  c0 * sw0);
                    float nc0 = fmaf(c0, cw0, -s0 * sw0);
                    float ns1 = fmaf(s1, cw1,  c1 * sw1);
                    float nc1 = fmaf(c1, cw1, -s1 * sw1);
                    float ns2 = fmaf(s2, cw2,  c2 * sw2);
                    float nc2 = fmaf(c2, cw2, -s2 * sw2);
                    s0 = ns0; c0 = nc0;
                    s1 = ns1; c1 = nc1;
                    s2 = ns2; c2 = nc2;
                }
                if (c + STAGES < NCHUNK) ISSUE(c + STAGES, s);
                #pragma unroll
                for (int k = 0; k < CHUNK; ++k)
                    __stcs(&out4[(row0 + c * CHUNK + k) * (DHID / 4) + t], o[k]);
            }
        }
        #undef ISSUE
        #undef WAITC
    } else {
        // tail fallback (not hit when N % ROWS_PER_CTA == 0)
        for (long long n = row0; n < rend; ++n) {
            const float pos = (float)(n + 1);
            float sA, cA, sB, cB;
            sincosf(pos * w1, &sA, &cA);
            sincosf(pos * w2, &sB, &cB);
            float c0v = __shfl_up_sync(0xFFFFFFFFu, cB, 1);
            if (lane == 0) c0v = cosf(pos * w0);
            const int idx = __ldg(&x[n]);
            float4 e = make_float4(0.f, 0.f, 0.f, 0.f);
            if (idx != 0) e = __ldg(&W4[(long long)idx * (DHID / 4) + t]);
            float4 o;
            o.x = e.x + c0v; o.y = e.y + sA; o.z = e.z + cA; o.w = e.w + sB;
            __stcs(&out4[n * (DHID / 4) + t], o);
        }
    }
}

extern "C" void kernel_launch(void* const* d_in, const int* in_sizes, int n_in,
                              void* d_out, int out_size)
{
    const int*   x   = (const int*)d_in[0];    // int32 [N]
    const float* W   = (const float*)d_in[1];  // f32 [V,1024]
    float*       out = (float*)d_out;          // f32 [N,1024]
    const int N = in_sizes[0];

    const int grid = (N + ROWS_PER_CTA - 1) / ROWS_PER_CTA;
    pe_embed_kernel<<<grid, TPB>>>(x, (const float4*)W, (float4*)out, N);
}

// round 11
// speedup vs baseline: 2.1416x; 2.1416x over previous
#include <cuda_runtime.h>
#include <math.h>

// out[n,j] = (x[n]==0 ? 0 : W[x[n],j]) + pe(n+1, j)
// pe(pos,j): even j -> cos(pos*w_{j/2}); odd j -> sin(pos*w_{(j+1)/2}); w_m = 1e-4^(m/512)
// Thread t owns cols 4t..4t+3. Warp-uniform EXACT (sincosf) / ROTATE (12 FMA) pe paths.
//
// R10: register-MLP gather (R4 lineage) +
//  - W gathers via createpolicy(evict_last) + ld.global.nc.L2::cache_hint.v4.f32
//    (direct .L2::evict_last qualifier is v8.b32/v4.b64-only on sm_103a ptxas;
//     the cache_hint+policy form has no shape restriction and ran fine in R4)
//  - prefetch.global.L2 of the NEXT chunk's rows (1 thread per 128B line)
//  - __stcs evict-first output stores

#define DHID 1024
#define TPB 256
#define ROWS_PER_CTA 32
#define UNROLL 4
#define ANGLE_T 3000.0f

__device__ __forceinline__ float4 ldg_hint(const float4* p, unsigned long long pol) {
    float4 v;
    asm volatile("ld.global.nc.L2::cache_hint.v4.f32 {%0,%1,%2,%3}, [%4], %5;"
                 : "=f"(v.x), "=f"(v.y), "=f"(v.z), "=f"(v.w) : "l"(p), "l"(pol));
    return v;
}

__device__ __forceinline__ void prefetch_l2(const void* p) {
    asm volatile("prefetch.global.L2 [%0];" :: "l"(p));
}

__global__ __launch_bounds__(TPB)
void pe_embed_kernel(const int* __restrict__ x,
                     const float4* __restrict__ W4,
                     float4* __restrict__ out4,
                     int N)
{
    const int t    = threadIdx.x;
    const int lane = t & 31;
    const long long row0 = (long long)blockIdx.x * (long long)ROWS_PER_CTA;
    if (row0 >= N) return;
    const long long rend = (row0 + ROWS_PER_CTA < (long long)N) ? row0 + ROWS_PER_CTA
                                                                : (long long)N;

    const float base   = 1.0f / 10000.0f;
    const float inv512 = 1.0f / 512.0f;
    const float w0 = powf(base, (float)(2 * t    ) * inv512);
    const float w1 = powf(base, (float)(2 * t + 1) * inv512);
    const float w2 = powf(base, (float)(2 * t + 2) * inv512);

    const float wmax  = __shfl_sync(0xFFFFFFFFu, w0, 0);
    const bool  exact = ((float)rend * wmax) > ANGLE_T;
    const bool  pfl   = ((t & 7) == 0);   // one thread per 128B line for prefetch

    unsigned long long pol;
    asm("createpolicy.fractional.L2::evict_last.b64 %0, 1.0;" : "=l"(pol));

    if ((rend - row0) == ROWS_PER_CTA) {
        int idx[UNROLL];
        #pragma unroll
        for (int k = 0; k < UNROLL; ++k) idx[k] = __ldg(&x[row0 + k]);
        if (pfl) {
            #pragma unroll
            for (int k = 0; k < UNROLL; ++k)
                if (idx[k] != 0) prefetch_l2(&W4[(long long)idx[k] * (DHID / 4) + t]);
        }

        if (exact) {
            for (long long n = row0; n < rend; n += UNROLL) {
                float4 e[UNROLL];
                #pragma unroll
                for (int k = 0; k < UNROLL; ++k) {
                    e[k] = make_float4(0.f, 0.f, 0.f, 0.f);
                    if (idx[k] != 0)
                        e[k] = ldg_hint(&W4[(long long)idx[k] * (DHID / 4) + t], pol);
                }
                if (n + UNROLL < rend) {
                    #pragma unroll
                    for (int k = 0; k < UNROLL; ++k) idx[k] = __ldg(&x[n + UNROLL + k]);
                    if (pfl) {
                        #pragma unroll
                        for (int k = 0; k < UNROLL; ++k)
                            if (idx[k] != 0)
                                prefetch_l2(&W4[(long long)idx[k] * (DHID / 4) + t]);
                    }
                }
                #pragma unroll
                for (int k = 0; k < UNROLL; ++k) {
                    const float pos = (float)(n + k + 1);
                    float sA, cA, sB, cB;
                    sincosf(pos * w1, &sA, &cA);
                    sincosf(pos * w2, &sB, &cB);
                    float c0v = __shfl_up_sync(0xFFFFFFFFu, cB, 1);
                    if (lane == 0) c0v = cosf(pos * w0);
                    float4 o;
                    o.x = e[k].x + c0v;
                    o.y = e[k].y + sA;
                    o.z = e[k].z + cA;
                    o.w = e[k].w + sB;
                    __stcs(&out4[(n + k) * (DHID / 4) + t], o);
                }
            }
        } else {
            const float pos0 = (float)(row0 + 1);
            float s0, c0, s1, c1, s2, c2;
            sincosf(pos0 * w0, &s0, &c0);
            sincosf(pos0 * w1, &s1, &c1);
            sincosf(pos0 * w2, &s2, &c2);
            float sw0, cw0, sw1, cw1, sw2, cw2;
            sincosf(w0, &sw0, &cw0);
            sincosf(w1, &sw1, &cw1);
            sincosf(w2, &sw2, &cw2);

            for (long long n = row0; n < rend; n += UNROLL) {
                float4 e[UNROLL];
                #pragma unroll
                for (int k = 0; k < UNROLL; ++k) {
                    e[k] = make_float4(0.f, 0.f, 0.f, 0.f);
                    if (idx[k] != 0)
                        e[k] = ldg_hint(&W4[(long long)idx[k] * (DHID / 4) + t], pol);
                }
                if (n + UNROLL < rend) {
                    #pragma unroll
                    for (int k = 0; k < UNROLL; ++k) idx[k] = __ldg(&x[n + UNROLL + k]);
                    if (pfl) {
                        #pragma unroll
                        for (int k = 0; k < UNROLL; ++k)
                            if (idx[k] != 0)
                                prefetch_l2(&W4[(long long)idx[k] * (DHID / 4) + t]);
                    }
                }
                #pragma unroll
                for (int k = 0; k < UNROLL; ++k) {
                    float4 o;
                    o.x = e[k].x + c0;
                    o.y = e[k].y + s1;
                    o.z = e[k].z + c1;
                    o.w = e[k].w + s2;
                    __stcs(&out4[(n + k) * (DHID / 4) + t], o);

                    float ns0 = fmaf(s0, cw0,  c0 * sw0);
                    float nc0 = fmaf(c0, cw0, -s0 * sw0);
                    float ns1 = fmaf(s1, cw1,  c1 * sw1);
                    float nc1 = fmaf(c1, cw1, -s1 * sw1);
                    float ns2 = fmaf(s2, cw2,  c2 * sw2);
                    float nc2 = fmaf(c2, cw2, -s2 * sw2);
                    s0 = ns0; c0 = nc0;
                    s1 = ns1; c1 = nc1;
                    s2 = ns2; c2 = nc2;
                }
            }
        }
    } else {
        // tail fallback (not hit when N % ROWS_PER_CTA == 0)
        for (long long n = row0; n < rend; ++n) {
            const float pos = (float)(n + 1);
            float sA, cA, sB, cB;
            sincosf(pos * w1, &sA, &cA);
            sincosf(pos * w2, &sB, &cB);
            float c0v = __shfl_up_sync(0xFFFFFFFFu, cB, 1);
            if (lane == 0) c0v = cosf(pos * w0);
            const int idx = __ldg(&x[n]);
            float4 e = make_float4(0.f, 0.f, 0.f, 0.f);
            if (idx != 0) e = __ldg(&W4[(long long)idx * (DHID / 4) + t]);
            float4 o;
            o.x = e.x + c0v; o.y = e.y + sA; o.z = e.z + cA; o.w = e.w + sB;
            __stcs(&out4[n * (DHID / 4) + t], o);
        }
    }
}

extern "C" void kernel_launch(void* const* d_in, const int* in_sizes, int n_in,
                              void* d_out, int out_size)
{
    const int*   x   = (const int*)d_in[0];    // int32 [N]
    const float* W   = (const float*)d_in[1];  // f32 [V,1024]
    float*       out = (float*)d_out;          // f32 [N,1024]
    const int N = in_sizes[0];

    const int grid = (N + ROWS_PER_CTA - 1) / ROWS_PER_CTA;
    pe_embed_kernel<<<grid, TPB>>>(x, (const float4*)W, (float4*)out, N);
}

// round 12
// speedup vs baseline: 2.2257x; 1.0393x over previous
#include <cuda_runtime.h>
#include <math.h>

// out[n,j] = (x[n]==0 ? 0 : W[x[n],j]) + pe(n+1, j)
// pe(pos,j): even j -> cos(pos*w_{j/2}); odd j -> sin(pos*w_{(j+1)/2}); w_m = 1e-4^(m/512)
// Thread t owns cols 4t..4t+3. Warp-uniform EXACT (sincosf) / ROTATE (12 FMA) pe paths.
//
// R11 = R4 (194.8us baseline: register MLP=4 gather, index prefetch, __stcs stores)
// with ONE change: ANGLE_T 3000 -> 25000. Measured rotate-error contribution at
// T=3000 was 8.6e-6 RMS (2.0708e-4 -> 2.0726e-4); linear scaling predicts ~7e-5 at
// T=25000 => total ~2.2e-4, 4.5x margin. Exact-path share drops ~37% -> ~13% of
// warps, freeing issue slots for the memory stream.
// (R10's evict_last + L2 prefetch were neutral/negative -> removed.)

#define DHID 1024
#define THREADS 256
#define ROWS_PER_CTA 32
#define UNROLL 4
#define ANGLE_T 25000.0f

__global__ __launch_bounds__(THREADS)
void pe_embed_kernel(const int* __restrict__ x,
                     const float4* __restrict__ W4,
                     float4* __restrict__ out4,
                     int N)
{
    const int t    = threadIdx.x;
    const int lane = t & 31;
    const long long row0 = (long long)blockIdx.x * ROWS_PER_CTA;
    if (row0 >= N) return;
    const long long rend = (row0 + ROWS_PER_CTA < (long long)N) ? row0 + ROWS_PER_CTA
                                                                : (long long)N;

    const float base   = 1.0f / 10000.0f;
    const float inv512 = 1.0f / 512.0f;
    const float w0 = powf(base, (float)(2 * t    ) * inv512);
    const float w1 = powf(base, (float)(2 * t + 1) * inv512);
    const float w2 = powf(base, (float)(2 * t + 2) * inv512);

    const float wmax  = __shfl_sync(0xFFFFFFFFu, w0, 0);
    const bool  exact = ((float)rend * wmax) > ANGLE_T;

    const bool full = ((rend - row0) % UNROLL) == 0;

    if (exact) {
        if (full) {
            int idx[UNROLL];
            #pragma unroll
            for (int k = 0; k < UNROLL; ++k) idx[k] = __ldg(&x[row0 + k]);

            for (long long n = row0; n < rend; n += UNROLL) {
                float4 e[UNROLL];
                #pragma unroll
                for (int k = 0; k < UNROLL; ++k) {
                    e[k] = make_float4(0.f, 0.f, 0.f, 0.f);
                    if (idx[k] != 0)
                        e[k] = __ldg(&W4[(long long)idx[k] * (DHID / 4) + t]);
                }
                if (n + UNROLL < rend) {
                    #pragma unroll
                    for (int k = 0; k < UNROLL; ++k) idx[k] = __ldg(&x[n + UNROLL + k]);
                }
                #pragma unroll
                for (int k = 0; k < UNROLL; ++k) {
                    const float pos = (float)(n + k + 1);
                    float sA, cA, sB, cB;
                    sincosf(pos * w1, &sA, &cA);
                    sincosf(pos * w2, &sB, &cB);
                    float c0 = __shfl_up_sync(0xFFFFFFFFu, cB, 1);
                    if (lane == 0) c0 = cosf(pos * w0);
                    float4 o;
                    o.x = e[k].x + c0;
                    o.y = e[k].y + sA;
                    o.z = e[k].z + cA;
                    o.w = e[k].w + sB;
                    __stcs(&out4[(n + k) * (DHID / 4) + t], o);
                }
            }
        } else {
            for (long long n = row0; n < rend; ++n) {
                const float pos = (float)(n + 1);
                float sA, cA, sB, cB;
                sincosf(pos * w1, &sA, &cA);
                sincosf(pos * w2, &sB, &cB);
                float c0 = __shfl_up_sync(0xFFFFFFFFu, cB, 1);
                if (lane == 0) c0 = cosf(pos * w0);
                const int idx = __ldg(&x[n]);
                float4 e = make_float4(0.f, 0.f, 0.f, 0.f);
                if (idx != 0) e = __ldg(&W4[(long long)idx * (DHID / 4) + t]);
                float4 o;
                o.x = e.x + c0; o.y = e.y + sA; o.z = e.z + cA; o.w = e.w + sB;
                __stcs(&out4[n * (DHID / 4) + t], o);
            }
        }
    } else {
        const float pos0 = (float)(row0 + 1);
        float s0, c0, s1, c1, s2, c2;
        sincosf(pos0 * w0, &s0, &c0);
        sincosf(pos0 * w1, &s1, &c1);
        sincosf(pos0 * w2, &s2, &c2);
        float sw0, cw0, sw1, cw1, sw2, cw2;
        sincosf(w0, &sw0, &cw0);
        sincosf(w1, &sw1, &cw1);
        sincosf(w2, &sw2, &cw2);

        if (full) {
            int idx[UNROLL];
            #pragma unroll
            for (int k = 0; k < UNROLL; ++k) idx[k] = __ldg(&x[row0 + k]);

            for (long long n = row0; n < rend; n += UNROLL) {
                float4 e[UNROLL];
                #pragma unroll
                for (int k = 0; k < UNROLL; ++k) {
                    e[k] = make_float4(0.f, 0.f, 0.f, 0.f);
                    if (idx[k] != 0)
                        e[k] = __ldg(&W4[(long long)idx[k] * (DHID / 4) + t]);
                }
                if (n + UNROLL < rend) {
                    #pragma unroll
                    for (int k = 0; k < UNROLL; ++k) idx[k] = __ldg(&x[n + UNROLL + k]);
                }
                #pragma unroll
                for (int k = 0; k < UNROLL; ++k) {
                    float4 o;
                    o.x = e[k].x + c0;
                    o.y = e[k].y + s1;
                    o.z = e[k].z + c1;
                    o.w = e[k].w + s2;
                    __stcs(&out4[(n + k) * (DHID / 4) + t], o);

                    float ns0 = fmaf(s0, cw0,  c0 * sw0);
                    float nc0 = fmaf(c0, cw0, -s0 * sw0);
                    float ns1 = fmaf(s1, cw1,  c1 * sw1);
                    float nc1 = fmaf(c1, cw1, -s1 * sw1);
                    float ns2 = fmaf(s2, cw2,  c2 * sw2);
                    float nc2 = fmaf(c2, cw2, -s2 * sw2);
                    s0 = ns0; c0 = nc0;
                    s1 = ns1; c1 = nc1;
                    s2 = ns2; c2 = nc2;
                }
            }
        } else {
            for (long long n = row0; n < rend; ++n) {
                const int idx = __ldg(&x[n]);
                float4 e = make_float4(0.f, 0.f, 0.f, 0.f);
                if (idx != 0) e = __ldg(&W4[(long long)idx * (DHID / 4) + t]);
                float4 o;
                o.x = e.x + c0; o.y = e.y + s1; o.z = e.z + c1; o.w = e.w + s2;
                __stcs(&out4[n * (DHID / 4) + t], o);

                float ns0 = fmaf(s0, cw0,  c0 * sw0);
                float nc0 = fmaf(c0, cw0, -s0 * sw0);
                float ns1 = fmaf(s1, cw1,  c1 * sw1);
                float nc1 = fmaf(c1, cw1, -s1 * sw1);
                float ns2 = fmaf(s2, cw2,  c2 * sw2);
                float nc2 = fmaf(c2, cw2, -s2 * sw2);
                s0 = ns0; c0 = nc0;
                s1 = ns1; c1 = nc1;
                s2 = ns2; c2 = nc2;
            }
        }
    }
}

extern "C" void kernel_launch(void* const* d_in, const int* in_sizes, int n_in,
                              void* d_out, int out_size)
{
    const int*   x   = (const int*)d_in[0];    // int32 [N]
    const float* W   = (const float*)d_in[1];  // f32 [V,1024]
    float*       out = (float*)d_out;          // f32 [N,1024]
    const int N = in_sizes[0];

    const int grid = (N + ROWS_PER_CTA - 1) / ROWS_PER_CTA;
    pe_embed_kernel<<<grid, THREADS>>>(x, (const float4*)W, (float4*)out, N);
}

// round 13
// speedup vs baseline: 2.2713x; 1.0205x over previous
#include <cuda_runtime.h>
#include <math.h>

// out[n,j] = (x[n]==0 ? 0 : W[x[n],j]) + pe(n+1, j)
// pe(pos,j): even j -> cos(pos*w_{j/2}); odd j -> sin(pos*w_{(j+1)/2}); w_m = 1e-4^(m/512)
//
// R12: L2-resident COLUMN SPLIT. Two sequential launches; pass p covers columns
// [p*512, p*512+512). Each pass's gather working set is a 103MB half of W, which
// fits the 126MB L2 -> gather misses become compulsory-only (~200MB total DRAM
// reads vs ~390MB measured for the monolithic kernel). W loads carry an
// evict_last cache hint; output stores are evict-first (__stcs). The pe numerics
// (EXACT sincosf / ROTATE 12-FMA split at ANGLE_T, thread->column mapping) are
// bit-identical to the 194.6us R11 kernel via the colq0 offset.

#define DHID 1024
#define TPB 128            // one float4 per thread across the 512-col half
#define ROWS_PER_CTA 32
#define UNROLL 4
#define ANGLE_T 25000.0f

__device__ __forceinline__ float4 ldg_hint(const float4* p, unsigned long long pol) {
    float4 v;
    asm volatile("ld.global.nc.L2::cache_hint.v4.f32 {%0,%1,%2,%3}, [%4], %5;"
                 : "=f"(v.x), "=f"(v.y), "=f"(v.z), "=f"(v.w) : "l"(p), "l"(pol));
    return v;
}

__global__ __launch_bounds__(TPB)
void pe_embed_half_kernel(const int* __restrict__ x,
                          const float4* __restrict__ W4,
                          float4* __restrict__ out4,
                          int N, int colq0)
{
    const int tl   = threadIdx.x;          // 0..127 within the half
    const int t    = colq0 + tl;           // global float4 index (0..255)
    const int lane = tl & 31;
    const long long row0 = (long long)blockIdx.x * ROWS_PER_CTA;
    if (row0 >= N) return;
    const long long rend = (row0 + ROWS_PER_CTA < (long long)N) ? row0 + ROWS_PER_CTA
                                                                : (long long)N;

    const float base   = 1.0f / 10000.0f;
    const float inv512 = 1.0f / 512.0f;
    const float w0 = powf(base, (float)(2 * t    ) * inv512);
    const float w1 = powf(base, (float)(2 * t + 1) * inv512);
    const float w2 = powf(base, (float)(2 * t + 2) * inv512);

    const float wmax  = __shfl_sync(0xFFFFFFFFu, w0, 0);
    const bool  exact = ((float)rend * wmax) > ANGLE_T;
    const bool  full  = ((rend - row0) % UNROLL) == 0;

    unsigned long long pol;
    asm("createpolicy.fractional.L2::evict_last.b64 %0, 1.0;" : "=l"(pol));

    if (exact) {
        if (full) {
            int idx[UNROLL];
            #pragma unroll
            for (int k = 0; k < UNROLL; ++k) idx[k] = __ldg(&x[row0 + k]);

            for (long long n = row0; n < rend; n += UNROLL) {
                float4 e[UNROLL];
                #pragma unroll
                for (int k = 0; k < UNROLL; ++k) {
                    e[k] = make_float4(0.f, 0.f, 0.f, 0.f);
                    if (idx[k] != 0)
                        e[k] = ldg_hint(&W4[(long long)idx[k] * (DHID / 4) + t], pol);
                }
                if (n + UNROLL < rend) {
                    #pragma unroll
                    for (int k = 0; k < UNROLL; ++k) idx[k] = __ldg(&x[n + UNROLL + k]);
                }
                #pragma unroll
                for (int k = 0; k < UNROLL; ++k) {
                    const float pos = (float)(n + k + 1);
                    float sA, cA, sB, cB;
                    sincosf(pos * w1, &sA, &cA);
                    sincosf(pos * w2, &sB, &cB);
                    float c0 = __shfl_up_sync(0xFFFFFFFFu, cB, 1);
                    if (lane == 0) c0 = cosf(pos * w0);
                    float4 o;
                    o.x = e[k].x + c0;
                    o.y = e[k].y + sA;
                    o.z = e[k].z + cA;
                    o.w = e[k].w + sB;
                    __stcs(&out4[(n + k) * (DHID / 4) + t], o);
                }
            }
        } else {
            for (long long n = row0; n < rend; ++n) {
                const float pos = (float)(n + 1);
                float sA, cA, sB, cB;
                sincosf(pos * w1, &sA, &cA);
                sincosf(pos * w2, &sB, &cB);
                float c0 = __shfl_up_sync(0xFFFFFFFFu, cB, 1);
                if (lane == 0) c0 = cosf(pos * w0);
                const int idx = __ldg(&x[n]);
                float4 e = make_float4(0.f, 0.f, 0.f, 0.f);
                if (idx != 0) e = ldg_hint(&W4[(long long)idx * (DHID / 4) + t], pol);
                float4 o;
                o.x = e.x + c0; o.y = e.y + sA; o.z = e.z + cA; o.w = e.w + sB;
                __stcs(&out4[n * (DHID / 4) + t], o);
            }
        }
    } else {
        const float pos0 = (float)(row0 + 1);
        float s0, c0, s1, c1, s2, c2;
        sincosf(pos0 * w0, &s0, &c0);
        sincosf(pos0 * w1, &s1, &c1);
        sincosf(pos0 * w2, &s2, &c2);
        float sw0, cw0, sw1, cw1, sw2, cw2;
        sincosf(w0, &sw0, &cw0);
        sincosf(w1, &sw1, &cw1);
        sincosf(w2, &sw2, &cw2);

        if (full) {
            int idx[UNROLL];
            #pragma unroll
            for (int k = 0; k < UNROLL; ++k) idx[k] = __ldg(&x[row0 + k]);

            for (long long n = row0; n < rend; n += UNROLL) {
                float4 e[UNROLL];
                #pragma unroll
                for (int k = 0; k < UNROLL; ++k) {
                    e[k] = make_float4(0.f, 0.f, 0.f, 0.f);
                    if (idx[k] != 0)
                        e[k] = ldg_hint(&W4[(long long)idx[k] * (DHID / 4) + t], pol);
                }
                if (n + UNROLL < rend) {
                    #pragma unroll
                    for (int k = 0; k < UNROLL; ++k) idx[k] = __ldg(&x[n + UNROLL + k]);
                }
                #pragma unroll
                for (int k = 0; k < UNROLL; ++k) {
                    float4 o;
                    o.x = e[k].x + c0;
                    o.y = e[k].y + s1;
                    o.z = e[k].z + c1;
                    o.w = e[k].w + s2;
                    __stcs(&out4[(n + k) * (DHID / 4) + t], o);

                    float ns0 = fmaf(s0, cw0,  c0 * sw0);
                    float nc0 = fmaf(c0, cw0, -s0 * sw0);
                    float ns1 = fmaf(s1, cw1,  c1 * sw1);
                    float nc1 = fmaf(c1, cw1, -s1 * sw1);
                    float ns2 = fmaf(s2, cw2,  c2 * sw2);
                    float nc2 = fmaf(c2, cw2, -s2 * sw2);
                    s0 = ns0; c0 = nc0;
                    s1 = ns1; c1 = nc1;
                    s2 = ns2; c2 = nc2;
                }
            }
        } else {
            for (long long n = row0; n < rend; ++n) {
                const int idx = __ldg(&x[n]);
                float4 e = make_float4(0.f, 0.f, 0.f, 0.f);
                if (idx != 0) e = ldg_hint(&W4[(long long)idx * (DHID / 4) + t], pol);
                float4 o;
                o.x = e.x + c0; o.y = e.y + s1; o.z = e.z + c1; o.w = e.w + s2;
                __stcs(&out4[n * (DHID / 4) + t], o);

                float ns0 = fmaf(s0, cw0,  c0 * sw0);
                float nc0 = fmaf(c0, cw0, -s0 * sw0);
                float ns1 = fmaf(s1, cw1,  c1 * sw1);
                float nc1 = fmaf(c1, cw1, -s1 * sw1);
                float ns2 = fmaf(s2, cw2,  c2 * sw2);
                float nc2 = fmaf(c2, cw2, -s2 * sw2);
                s0 = ns0; c0 = nc0;
                s1 = ns1; c1 = nc1;
                s2 = ns2; c2 = nc2;
            }
        }
    }
}

extern "C" void kernel_launch(void* const* d_in, const int* in_sizes, int n_in,
                              void* d_out, int out_size)
{
    const int*   x   = (const int*)d_in[0];    // int32 [N]
    const float* W   = (const float*)d_in[1];  // f32 [V,1024]
    float*       out = (float*)d_out;          // f32 [N,1024]
    const int N = in_sizes[0];

    const int grid = (N + ROWS_PER_CTA - 1) / ROWS_PER_CTA;
    // Two sequential passes; each pass's 103MB half of W is L2-resident.
    pe_embed_half_kernel<<<grid, TPB>>>(x, (const float4*)W, (float4*)out, N, 0);
    pe_embed_half_kernel<<<grid, TPB>>>(x, (const float4*)W, (float4*)out, N, 128);
}